// round 6
// baseline (speedup 1.0000x reference)
#include <cuda_runtime.h>
#include <math.h>

#define BB 16
#define TT 12
#define NN 300
#define DD 64
#define TW 10
#define NWIN (BB*TW)     // 160
#define NBT  (BB*TT)     // 192
#define K1C  3
#define K1R  100
#define K1_BLOCKS (NBT*K1C)   // 576

__device__ float g_wf [NBT*NN*DD];
__device__ float g_Mtp[K1_BLOCKS*DD*DD];
__device__ float g_ksp[K1_BLOCKS*DD];
__device__ float g_MW [NWIN*DD*DD];
__device__ float g_ksw[NWIN*DD];

typedef unsigned long long ull;

__device__ __forceinline__ ull pack2(float x) {
    ull r; asm("mov.b64 %0, {%1, %1};" : "=l"(r) : "f"(x)); return r;
}
__device__ __forceinline__ void ffma2(ull& d, ull a, ull b) {
    asm("fma.rn.f32x2 %0, %1, %2, %0;" : "+l"(d) : "l"(a), "l"(b));
}
__device__ __forceinline__ float2 unpk2(ull v) {
    float2 r; asm("mov.b64 {%0, %1}, %2;" : "=f"(r.x), "=f"(r.y) : "l"(v)); return r;
}

extern __shared__ float s_dyn[];

// ---------------------------------------------------------------------------
// k1: per (b,t, chunk of 100 rows): gate+normalize (store wf), then
// rank-1 accumulate partial M (FFMA2) and partial ksum.
// dyn smem: se[100*64] raw feat rows, su[100*64] u=inv*e, gws[64]
// ---------------------------------------------------------------------------
__global__ void __launch_bounds__(128) k1(const float* __restrict__ feat,
                                          const float* __restrict__ weights) {
    float* se  = s_dyn;               // 6400
    float* su  = se + K1R*DD;         // 6400
    float* gws = su + K1R*DD;         // 64
    const int tid = threadIdx.x, bid = blockIdx.x;
    const int bt = bid / K1C, chunk = bid - bt*K1C;
    const int base = (bt*NN + chunk*K1R)*DD;

    if (tid < DD) gws[tid] = 1.f/(1.f + expf(-weights[tid]));
    {
        const float4* fsrc = (const float4*)(feat + base);
        float4* sdst = (float4*)se;
        for (int idx = tid; idx < K1R*DD/4; idx += 128) sdst[idx] = fsrc[idx];
    }
    __syncthreads();

    {   // per-row inverse norm; write wf to global, u to smem
        const int wid = tid >> 5, lane = tid & 31;
        for (int r = wid; r < K1R; r += 4) {
            float e0 = se[r*DD + lane], e1 = se[r*DD + 32 + lane];
            float g0 = gws[lane]*e0, g1 = gws[lane+32]*e1;
            float ss = g0*g0 + g1*g1;
            #pragma unroll
            for (int o = 16; o; o >>= 1) ss += __shfl_xor_sync(0xffffffffu, ss, o);
            float inv = 1.f / fmaxf(sqrtf(ss), 1e-12f);
            g_wf[base + r*DD + lane]      = g0*inv;
            g_wf[base + r*DD + 32 + lane] = g1*inv;
            su[r*DD + lane]      = e0*inv;
            su[r*DD + 32 + lane] = e1*inv;
        }
    }
    __syncthreads();

    // gram accumulation: 4(i) x 8(j) tile per thread, 16x8 thread grid
    const int tx = tid & 15, ty = tid >> 4;     // tx:0..15, ty:0..7
    const int i0 = tx*4, j0 = ty*8;
    ull a00=0,a01=0,a02=0,a03=0;
    ull a10=0,a11=0,a12=0,a13=0;
    ull a20=0,a21=0,a22=0,a23=0;
    ull a30=0,a31=0,a32=0,a33=0;
    float ks0=0.f, ks1=0.f, ks2=0.f, ks3=0.f;

    for (int r = 0; r < K1R; r++) {
        float4 uv = *(const float4*)(su + r*DD + i0);
        ulonglong2 eA = *(const ulonglong2*)(se + r*DD + j0);
        ulonglong2 eB = *(const ulonglong2*)(se + r*DD + j0 + 4);
        ull u0 = pack2(uv.x), u1 = pack2(uv.y), u2 = pack2(uv.z), u3 = pack2(uv.w);
        ffma2(a00,u0,eA.x); ffma2(a01,u0,eA.y); ffma2(a02,u0,eB.x); ffma2(a03,u0,eB.y);
        ffma2(a10,u1,eA.x); ffma2(a11,u1,eA.y); ffma2(a12,u1,eB.x); ffma2(a13,u1,eB.y);
        ffma2(a20,u2,eA.x); ffma2(a21,u2,eA.y); ffma2(a22,u2,eB.x); ffma2(a23,u2,eB.y);
        ffma2(a30,u3,eA.x); ffma2(a31,u3,eA.y); ffma2(a32,u3,eB.x); ffma2(a33,u3,eB.y);
        if (ty == 0) { ks0 += uv.x; ks1 += uv.y; ks2 += uv.z; ks3 += uv.w; }
    }

    float* Mout = g_Mtp + bid*DD*DD;
    #pragma unroll
    for (int a = 0; a < 4; a++) {
        ull r0, r1, r2, r3;
        if (a == 0) { r0=a00; r1=a01; r2=a02; r3=a03; }
        else if (a == 1) { r0=a10; r1=a11; r2=a12; r3=a13; }
        else if (a == 2) { r0=a20; r1=a21; r2=a22; r3=a23; }
        else { r0=a30; r1=a31; r2=a32; r3=a33; }
        float gw = gws[i0 + a];
        float2 p0 = unpk2(r0), p1 = unpk2(r1), p2 = unpk2(r2), p3 = unpk2(r3);
        float4 o0 = make_float4(gw*p0.x, gw*p0.y, gw*p1.x, gw*p1.y);
        float4 o1 = make_float4(gw*p2.x, gw*p2.y, gw*p3.x, gw*p3.y);
        *(float4*)(Mout + (i0+a)*DD + j0)     = o0;
        *(float4*)(Mout + (i0+a)*DD + j0 + 4) = o1;
    }
    if (ty == 0) {
        float* kso = g_ksp + bid*DD + i0;
        kso[0] = gws[i0+0]*ks0; kso[1] = gws[i0+1]*ks1;
        kso[2] = gws[i0+2]*ks2; kso[3] = gws[i0+3]*ks3;
    }
}

// ---------------------------------------------------------------------------
// k1b: per window: M = sum of 9 partials; MW = M@w1; ksw = sum of ksum partials
// ---------------------------------------------------------------------------
__global__ void __launch_bounds__(256) k1b(const float* __restrict__ w1) {
    __shared__ float Ms [DD*DD];
    __shared__ float w1s[DD*DD];
    const int tid = threadIdx.x, w = blockIdx.x;
    const int b = w / TW, t2 = w - b*TW;
    const int bt0 = b*TT + t2;

    for (int idx = tid; idx < DD*DD; idx += 256) {
        float s = 0.f;
        #pragma unroll
        for (int dt = 0; dt < 3; dt++)
            #pragma unroll
            for (int c = 0; c < K1C; c++)
                s += g_Mtp[((bt0+dt)*K1C + c)*DD*DD + idx];
        Ms[idx] = s;
        w1s[idx] = w1[idx];
    }
    if (tid < DD) {
        float s = 0.f;
        #pragma unroll
        for (int dt = 0; dt < 3; dt++)
            #pragma unroll
            for (int c = 0; c < K1C; c++)
                s += g_ksp[((bt0+dt)*K1C + c)*DD + tid];
        g_ksw[w*DD + tid] = s;
    }
    __syncthreads();

    const int tx = tid & 15, ty = tid >> 4;
    const int i0 = ty*4, j0 = tx*4;
    float acc[4][4];
    #pragma unroll
    for (int a = 0; a < 4; a++)
        #pragma unroll
        for (int q = 0; q < 4; q++) acc[a][q] = 0.f;
    for (int k = 0; k < DD; k++) {
        float av[4], bv[4];
        #pragma unroll
        for (int a = 0; a < 4; a++) av[a] = Ms[(i0+a)*DD + k];
        #pragma unroll
        for (int q = 0; q < 4; q++) bv[q] = w1s[k*DD + j0+q];
        #pragma unroll
        for (int a = 0; a < 4; a++)
            #pragma unroll
            for (int q = 0; q < 4; q++) acc[a][q] += av[a]*bv[q];
    }
    float* MWo = g_MW + w*DD*DD;
    #pragma unroll
    for (int a = 0; a < 4; a++)
        #pragma unroll
        for (int q = 0; q < 4; q++) MWo[(i0+a)*DD + j0+q] = acc[a][q];
}

// ---------------------------------------------------------------------------
// k2: 2 rows x 16 lanes x 4 cols per lane. FFMA2 GEMVs + residual + LN.
// dyn smem: sMW[4096], sW2[4096], sQ[100*64]
// ---------------------------------------------------------------------------
__device__ __forceinline__ void gemv64x2(const float* __restrict__ row,
                                         const float* __restrict__ W, int c0,
                                         ull& a0, ull& a1) {
    a0 = 0; a1 = 0;
    #pragma unroll
    for (int i4 = 0; i4 < 16; i4++) {
        float4 q4 = *(const float4*)(row + i4*4);
        ull qd; ulonglong2 m;
        qd = pack2(q4.x); m = *(const ulonglong2*)(W + (i4*4+0)*DD + c0); ffma2(a0,qd,m.x); ffma2(a1,qd,m.y);
        qd = pack2(q4.y); m = *(const ulonglong2*)(W + (i4*4+1)*DD + c0); ffma2(a0,qd,m.x); ffma2(a1,qd,m.y);
        qd = pack2(q4.z); m = *(const ulonglong2*)(W + (i4*4+2)*DD + c0); ffma2(a0,qd,m.x); ffma2(a1,qd,m.y);
        qd = pack2(q4.w); m = *(const ulonglong2*)(W + (i4*4+3)*DD + c0); ffma2(a0,qd,m.x); ffma2(a1,qd,m.y);
    }
}

__global__ void __launch_bounds__(128) k2(const float* __restrict__ feat,
                                          const float* __restrict__ b1,
                                          const float* __restrict__ w2,
                                          const float* __restrict__ b2,
                                          const float* __restrict__ gamma,
                                          const float* __restrict__ beta,
                                          float* __restrict__ out) {
    float* sMW = s_dyn;           // 4096
    float* sW2 = sMW + 4096;      // 4096
    float* sQ  = sW2 + 4096;      // 6400

    const int tid = threadIdx.x, bid = blockIdx.x;
    const int w = bid / 3, chunk = bid - w*3;
    const int b = w / TW, t2 = w - b*TW;
    const int tile = b*TT + t2 + 2;
    const int rowbase = (tile*NN + chunk*100)*DD;

    {
        float4* dMW = (float4*)sMW; const float4* gMW = (const float4*)(g_MW + w*4096);
        float4* dW2 = (float4*)sW2; const float4* gW2 = (const float4*)w2;
        for (int idx = tid; idx < 1024; idx += 128) { dMW[idx] = gMW[idx]; dW2[idx] = gW2[idx]; }
        float4* dQ = (float4*)sQ; const float4* gQ = (const float4*)(g_wf + rowbase);
        for (int idx = tid; idx < 1600; idx += 128) dQ[idx] = gQ[idx];
    }

    const int wid = tid >> 5, lane = tid & 31;
    const int g = lane >> 4, l = lane & 15;
    const int c0 = 4*l;
    float4 ksg = *(const float4*)(g_ksw + w*DD + c0);
    float4 b1g = *(const float4*)(b1 + c0);
    float4 b2g = *(const float4*)(b2 + c0);
    float4 gag = *(const float4*)(gamma + c0);
    float4 beg = *(const float4*)(beta + c0);
    __syncthreads();

    for (int rb = wid*2; rb < 100; rb += 8) {
        const int r = rb + g;
        float* qrow = sQ + r*DD;

        // deg = q . ksum  (16-lane group reduction)
        float4 qv = *(const float4*)(qrow + c0);
        float d = qv.x*ksg.x + qv.y*ksg.y + qv.z*ksg.z + qv.w*ksg.w;
        d += __shfl_xor_sync(0xffffffffu, d, 1);
        d += __shfl_xor_sync(0xffffffffu, d, 2);
        d += __shfl_xor_sync(0xffffffffu, d, 4);
        d += __shfl_xor_sync(0xffffffffu, d, 8);
        float dinv = (d == 0.f) ? 0.f : 1.f/d;

        // GEMV1: h = relu(dinv * q @ MW + b1)
        ull a0, a1;
        gemv64x2(qrow, sMW, c0, a0, a1);
        float2 h01 = unpk2(a0), h23 = unpk2(a1);
        float4 h;
        h.x = fmaxf(h01.x*dinv + b1g.x, 0.f);
        h.y = fmaxf(h01.y*dinv + b1g.y, 0.f);
        h.z = fmaxf(h23.x*dinv + b1g.z, 0.f);
        h.w = fmaxf(h23.y*dinv + b1g.w, 0.f);
        __syncwarp();
        *(float4*)(qrow + c0) = h;
        __syncwarp();

        // GEMV2: v = h @ W2 + b2 + feat
        gemv64x2(qrow, sW2, c0, a0, a1);
        float2 v01 = unpk2(a0), v23 = unpk2(a1);
        float4 f4 = *(const float4*)(feat + rowbase + r*DD + c0);
        float v0 = v01.x + b2g.x + f4.x;
        float v1 = v01.y + b2g.y + f4.y;
        float v2 = v23.x + b2g.z + f4.z;
        float v3 = v23.y + b2g.w + f4.w;

        // LayerNorm over 64 (16-lane group holds the row)
        float s = v0 + v1 + v2 + v3;
        s += __shfl_xor_sync(0xffffffffu, s, 1);
        s += __shfl_xor_sync(0xffffffffu, s, 2);
        s += __shfl_xor_sync(0xffffffffu, s, 4);
        s += __shfl_xor_sync(0xffffffffu, s, 8);
        float mu = s * (1.f/DD);
        float q0 = v0-mu, q1 = v1-mu, q2 = v2-mu, q3 = v3-mu;
        float ss = q0*q0 + q1*q1 + q2*q2 + q3*q3;
        ss += __shfl_xor_sync(0xffffffffu, ss, 1);
        ss += __shfl_xor_sync(0xffffffffu, ss, 2);
        ss += __shfl_xor_sync(0xffffffffu, ss, 4);
        ss += __shfl_xor_sync(0xffffffffu, ss, 8);
        float rs = rsqrtf(ss * (1.f/DD) + 1e-5f);

        float4 o;
        o.x = q0*rs*gag.x + beg.x;
        o.y = q1*rs*gag.y + beg.y;
        o.z = q2*rs*gag.z + beg.z;
        o.w = q3*rs*gag.w + beg.w;
        *(float4*)(out + (w*NN + chunk*100 + r)*DD + c0) = o;
    }
}

extern "C" void kernel_launch(void* const* d_in, const int* in_sizes, int n_in,
                              void* d_out, int out_size) {
    const float* feat    = (const float*)d_in[0];
    const float* weights = (const float*)d_in[1];
    const float* w1      = (const float*)d_in[2];
    const float* b1      = (const float*)d_in[3];
    const float* w2      = (const float*)d_in[4];
    const float* b2      = (const float*)d_in[5];
    const float* gamma   = (const float*)d_in[6];
    const float* beta    = (const float*)d_in[7];
    float* out = (float*)d_out;

    size_t smem1 = (2*K1R*DD + DD) * sizeof(float);          // ~51.5KB
    size_t smem2 = (4096 + 4096 + 100*DD) * sizeof(float);   // ~58.4KB
    static bool attr_set = false;
    if (!attr_set) {
        cudaFuncSetAttribute(k1, cudaFuncAttributeMaxDynamicSharedMemorySize, (int)smem1);
        cudaFuncSetAttribute(k2, cudaFuncAttributeMaxDynamicSharedMemorySize, (int)smem2);
        attr_set = true;
    }
    k1 <<<K1_BLOCKS, 128, smem1>>>(feat, weights);
    k1b<<<NWIN, 256>>>(w1);
    k2 <<<NWIN*3, 128, smem2>>>(feat, b1, w2, b2, gamma, beta, out);
}